// round 15
// baseline (speedup 1.0000x reference)
#include <cuda_runtime.h>
#include <cuda_bf16.h>
#include <cstdint>
#include <math.h>

#define NNODE 8192
#define NEDGE 262144
#define KF    512
#define NH    512
#define NO    64

#define NCHUNK 24              // K=1536 bf16 in chunks of 64
#define NSTAGE 3
#define STAGE_BYTES 32768      // A 16KB + B 16KB per stage
#define SMEM_TOTAL (NSTAGE * STAGE_BYTES)   // 98304

// ---------------- scratch ----------------
__device__ float g_buf1[NNODE * NH];
__device__ float g_buf3[NNODE * NH];
__device__ float g_xhid[NNODE * NH];
__device__ float g_dinv[NNODE];
__device__ int   g_cnt [NNODE];
__device__ int   g_off [NNODE + 1];
__device__ int   g_cur [NNODE];
__device__ int   g_ssrc[NEDGE];
__device__ __nv_bfloat16 g_Ahi[NNODE * NH];
__device__ __nv_bfloat16 g_Alo[NNODE * NH];
__device__ __nv_bfloat16 g_Whi[NH * NH];
__device__ __nv_bfloat16 g_Wlo[NH * NH];

// ---------------- PTX helpers ----------------
__device__ __forceinline__ uint32_t smem_u32(const void* p) {
    uint32_t a;
    asm("{ .reg .u64 t; cvta.to.shared.u64 t, %1; cvt.u32.u64 %0, t; }" : "=r"(a) : "l"(p));
    return a;
}
__device__ __forceinline__ void cp_async16(uint32_t saddr, const void* g) {
    asm volatile("cp.async.cg.shared.global [%0], [%1], 16;" :: "r"(saddr), "l"(g) : "memory");
}
__device__ __forceinline__ void cp_commit() {
    asm volatile("cp.async.commit_group;" ::: "memory");
}
template <int N> __device__ __forceinline__ void cp_wait() {
    asm volatile("cp.async.wait_group %0;" :: "n"(N) : "memory");
}
__device__ __forceinline__ void ldsm_x4(uint32_t& r0, uint32_t& r1, uint32_t& r2, uint32_t& r3,
                                        uint32_t a) {
    asm volatile("ldmatrix.sync.aligned.m8n8.x4.shared.b16 {%0,%1,%2,%3}, [%4];"
                 : "=r"(r0), "=r"(r1), "=r"(r2), "=r"(r3) : "r"(a));
}
__device__ __forceinline__ void mma_bf16(float* d, const uint32_t* a, const uint32_t* b) {
    asm volatile(
        "mma.sync.aligned.m16n8k16.row.col.f32.bf16.bf16.f32 "
        "{%0,%1,%2,%3}, {%4,%5,%6,%7}, {%8,%9}, {%0,%1,%2,%3};"
        : "+f"(d[0]), "+f"(d[1]), "+f"(d[2]), "+f"(d[3])
        : "r"(a[0]), "r"(a[1]), "r"(a[2]), "r"(a[3]), "r"(b[0]), "r"(b[1]));
}
__device__ __forceinline__ void stg_cs_64(float* p, float a, float b) {
    float2 v = make_float2(a, b);
    asm volatile("st.global.cs.v2.f32 [%0], {%1, %2};" :: "l"(p), "f"(v.x), "f"(v.y) : "memory");
}
__device__ __forceinline__ void stg_cs_128(float* p, float4 v) {
    asm volatile("st.global.cs.v4.f32 [%0], {%1, %2, %3, %4};"
                 :: "l"(p), "f"(v.x), "f"(v.y), "f"(v.z), "f"(v.w) : "memory");
}

// ---------------- CSR build ----------------
__global__ void k_zero() {
    int i = blockIdx.x * blockDim.x + threadIdx.x;
    if (i < NNODE) g_cnt[i] = 0;
}
__global__ void k_count(const int* __restrict__ dst) {
    int i = blockIdx.x * blockDim.x + threadIdx.x;
    if (i < NEDGE) atomicAdd(&g_cnt[dst[i]], 1);
}
__global__ void k_scan() {
    __shared__ int ssum[1024];
    int t = threadIdx.x;
    int base = t * 8;
    int c[8];
    int s = 0;
#pragma unroll
    for (int i = 0; i < 8; i++) { c[i] = g_cnt[base + i]; s += c[i]; }
    ssum[t] = s;
    __syncthreads();
    for (int off = 1; off < 1024; off <<= 1) {
        int v = (t >= off) ? ssum[t - off] : 0;
        __syncthreads();
        ssum[t] += v;
        __syncthreads();
    }
    int excl = ssum[t] - s;
#pragma unroll
    for (int i = 0; i < 8; i++) {
        g_off[base + i] = excl;
        g_cur[base + i] = excl;
        g_dinv[base + i] = rsqrtf((float)c[i] + 1.0f);
        excl += c[i];
    }
    if (t == 1023) g_off[NNODE] = ssum[1023];
}
__global__ void k_fill(const int* __restrict__ src, const int* __restrict__ dst) {
    int i = blockIdx.x * blockDim.x + threadIdx.x;
    if (i < NEDGE) {
        int p = atomicAdd(&g_cur[dst[i]], 1);
        g_ssrc[p] = src[i];
    }
}

// ---------------- split fp32 -> bf16 hi/lo (for x only) ----------------
__global__ void k_splitF(const float* __restrict__ X,
                         __nv_bfloat16* __restrict__ H, __nv_bfloat16* __restrict__ L) {
    int i = (blockIdx.x * blockDim.x + threadIdx.x) * 4;
    float4 v = *(const float4*)(X + i);
    __nv_bfloat16 h0 = __float2bfloat16(v.x), h1 = __float2bfloat16(v.y);
    __nv_bfloat16 h2 = __float2bfloat16(v.z), h3 = __float2bfloat16(v.w);
    __nv_bfloat162* H2 = (__nv_bfloat162*)(H + i);
    H2[0] = __nv_bfloat162(h0, h1);
    H2[1] = __nv_bfloat162(h2, h3);
    __nv_bfloat16 l0 = __float2bfloat16(v.x - __bfloat162float(h0));
    __nv_bfloat16 l1 = __float2bfloat16(v.y - __bfloat162float(h1));
    __nv_bfloat16 l2 = __float2bfloat16(v.z - __bfloat162float(h2));
    __nv_bfloat16 l3 = __float2bfloat16(v.w - __bfloat162float(h3));
    __nv_bfloat162* L2 = (__nv_bfloat162*)(L + i);
    L2[0] = __nv_bfloat162(l0, l1);
    L2[1] = __nv_bfloat162(l2, l3);
}

// ---------------- transpose + split W[512,512] ----------------
__global__ void k_prepW(const float* __restrict__ W,
                        __nv_bfloat16* __restrict__ TH, __nv_bfloat16* __restrict__ TL) {
    __shared__ float t[32][33];
    int tx = threadIdx.x, ty = threadIdx.y;
    int k0 = blockIdx.x * 32, n0 = blockIdx.y * 32;
    t[ty][tx] = W[(size_t)(k0 + ty) * NH + n0 + tx];
    __syncthreads();
    float v = t[tx][ty];
    __nv_bfloat16 h = __float2bfloat16(v);
    __nv_bfloat16 l = __float2bfloat16(v - __bfloat162float(h));
    TH[(size_t)(n0 + ty) * NH + k0 + tx] = h;
    TL[(size_t)(n0 + ty) * NH + k0 + tx] = l;
}

// ---------------- HMMA GEMM: 128x128 tile, 256 thr, 8 warps, 3-stage ----------------
// MODE 0: C = A @ B^T plain (2D grid). MODE 1: symmetric dis, triangular 1D grid,
//         evict-first (.cs) output stores.
__device__ __forceinline__ void load_chunk(
    const __nv_bfloat16* __restrict__ Asrc, const __nv_bfloat16* __restrict__ Bsrc,
    int rowbA, int rowbB, int kbyte, uint32_t sA, int tid)
{
#pragma unroll
    for (int j = 0; j < 4; j++) {
        int u = tid + 256 * j;               // 0..1023
        int r = u >> 3, q = u & 7;
        int off = r * 128 + ((q * 16) ^ ((r & 7) * 16));
        cp_async16(sA + off,         (const char*)Asrc + (size_t)(rowbA + r) * 1024 + kbyte + q * 16);
        cp_async16(sA + 16384 + off, (const char*)Bsrc + (size_t)(rowbB + r) * 1024 + kbyte + q * 16);
    }
}

template <int MODE>
__global__ __launch_bounds__(256, 2) void k_mma_gemm(
    const __nv_bfloat16* __restrict__ Ahi, const __nv_bfloat16* __restrict__ Alo,
    const __nv_bfloat16* __restrict__ Bhi, const __nv_bfloat16* __restrict__ Blo,
    float* __restrict__ C, int ldc)
{
    int bx, by;
    if (MODE == 1) {
        // triangular unrank: id = bx*(bx+1)/2 + by, by <= bx
        int id = blockIdx.x;
        int b = (int)((sqrtf(8.0f * (float)id + 1.0f) - 1.0f) * 0.5f);
        while ((b + 1) * (b + 2) / 2 <= id) ++b;
        while (b * (b + 1) / 2 > id) --b;
        bx = b;
        by = id - b * (b + 1) / 2;
    } else {
        bx = blockIdx.x;
        by = blockIdx.y;
    }

    extern __shared__ char smem[];
    uint32_t sb = smem_u32(smem);
    int tid = threadIdx.x;
    int lane = tid & 31, wid = tid >> 5;
    int wm = wid & 1, wn = wid >> 1;         // warp tile: rows wm*64, cols wn*32

    int rowbA = by * 128;
    int rowbB = bx * 128;

    float acc[4][4][4];
#pragma unroll
    for (int mt = 0; mt < 4; mt++)
#pragma unroll
        for (int nt = 0; nt < 4; nt++)
#pragma unroll
            for (int e = 0; e < 4; e++) acc[mt][nt][e] = 0.f;

    int arow = wm * 64 + (lane & 15);
    int akb  = (lane >> 4) * 16;
    int brow = wn * 32 + ((lane >> 4) << 3) + (lane & 7);  // x4: lanes 0-15 n0-7, 16-31 n8-15
    int bkb  = ((lane >> 3) & 1) * 16;

    // prologue: 2 chunks in flight
    load_chunk(Ahi, Bhi, rowbA, rowbB, 0, sb, tid);
    cp_commit();
    load_chunk(Ahi, Bhi, rowbA, rowbB, 128, sb + STAGE_BYTES, tid);
    cp_commit();

    for (int c = 0; c < NCHUNK; c++) {
        if (c < NCHUNK - 1) cp_wait<1>();
        else                cp_wait<0>();
        __syncthreads();
        if (c + 2 < NCHUNK) {
            int cn = c + 2;
            int part = cn >> 3;
            const __nv_bfloat16* As = (part == 1) ? Alo : Ahi;
            const __nv_bfloat16* Bs = (part == 2) ? Blo : Bhi;
            load_chunk(As, Bs, rowbA, rowbB, (cn & 7) * 128, sb + (cn % NSTAGE) * STAGE_BYTES, tid);
            cp_commit();
        }

        uint32_t stA = sb + (c % NSTAGE) * STAGE_BYTES;
        uint32_t stB = stA + 16384;
#pragma unroll
        for (int kt = 0; kt < 4; kt++) {
            uint32_t af[4][4], bf[4][2];
#pragma unroll
            for (int mt = 0; mt < 4; mt++) {
                int r = arow + mt * 16;
                int kb = kt * 32 + akb;
                uint32_t ad = stA + r * 128 + (kb ^ ((r & 7) * 16));
                ldsm_x4(af[mt][0], af[mt][1], af[mt][2], af[mt][3], ad);
            }
#pragma unroll
            for (int ntp = 0; ntp < 2; ntp++) {
                int r = brow + ntp * 16;
                int kb = kt * 32 + bkb;
                uint32_t bd = stB + r * 128 + (kb ^ ((r & 7) * 16));
                ldsm_x4(bf[2 * ntp][0], bf[2 * ntp][1], bf[2 * ntp + 1][0], bf[2 * ntp + 1][1], bd);
            }
#pragma unroll
            for (int mt = 0; mt < 4; mt++)
#pragma unroll
                for (int nt = 0; nt < 4; nt++)
                    mma_bf16(acc[mt][nt], af[mt], bf[nt]);
        }
    }

    // ---------------- epilogue ----------------
    int lr0 = wm * 64 + (lane >> 2);
    int lc0 = wn * 32 + (lane & 3) * 2;
    float* T = (float*)smem;                 // [128][132] transpose buffer (MODE 1)
    if (MODE == 1) __syncthreads();

#pragma unroll
    for (int mt = 0; mt < 4; mt++) {
#pragma unroll
        for (int nt = 0; nt < 4; nt++) {
            float* a = acc[mt][nt];
            int lr = lr0 + mt * 16;
            int lc = lc0 + nt * 8;
            if (MODE == 1 && bx == by) {
                if (lr == lc) a[0] = 0.f;
                if (lr == lc + 1) a[1] = 0.f;
                if (lr + 8 == lc) a[2] = 0.f;
                if (lr + 8 == lc + 1) a[3] = 0.f;
            }
            size_t g0 = (size_t)(by * 128 + lr) * ldc + bx * 128 + lc;
            if (MODE == 1) {
                stg_cs_64(&C[g0], a[0], a[1]);
                stg_cs_64(&C[g0 + 8 * ldc], a[2], a[3]);
            } else {
                *(float2*)&C[g0] = make_float2(a[0], a[1]);
                *(float2*)&C[g0 + 8 * ldc] = make_float2(a[2], a[3]);
            }
            if (MODE == 1 && bx != by) {
                T[lc * 132 + lr] = a[0];
                T[(lc + 1) * 132 + lr] = a[1];
                T[lc * 132 + lr + 8] = a[2];
                T[(lc + 1) * 132 + lr + 8] = a[3];
            }
        }
    }

    if (MODE == 1 && bx != by) {
        __syncthreads();
        // coalesced mirror write-out: each warp writes one contiguous 512B row
        // segment per iteration (8 warps x 16 iters = 128 rows)
#pragma unroll
        for (int it = 0; it < 16; it++) {
            int mrow = wid + it * 8;
            const float* Tr = &T[mrow * 132 + lane * 4];
            float4 v = make_float4(Tr[0], Tr[1], Tr[2], Tr[3]);
            stg_cs_128(&C[(size_t)(bx * 128 + mrow) * ldc + by * 128 + lane * 4], v);
        }
    }
}

// ---------------- GCN aggregation (unroll-8, 8 gathers in flight) ----------------
// OUTS=1: conv1 -> relu -> bf16 hi/lo split (conv2 input)
// OUTS=2: conv2 -> relu -> pxh (fp32, for fc) + L2-normalized bf16 hi/lo split (dis input)
template <int OUTS>
__global__ __launch_bounds__(128) void k_agg(
    const float* __restrict__ h, const float* __restrict__ bias,
    float* __restrict__ out, __nv_bfloat16* __restrict__ OH, __nv_bfloat16* __restrict__ OL)
{
    __shared__ float red[4];
    int d = blockIdx.x;
    int t = threadIdx.x;
    const float4* h4 = (const float4*)h;
    float4 a0 = make_float4(0.f, 0.f, 0.f, 0.f);
    float4 a1 = make_float4(0.f, 0.f, 0.f, 0.f);
    float4 a2 = make_float4(0.f, 0.f, 0.f, 0.f);
    float4 a3 = make_float4(0.f, 0.f, 0.f, 0.f);
    int e = g_off[d], end = g_off[d + 1];
    for (; e + 8 <= end; e += 8) {
        int s0 = g_ssrc[e],     s1 = g_ssrc[e + 1], s2 = g_ssrc[e + 2], s3 = g_ssrc[e + 3];
        int s4 = g_ssrc[e + 4], s5 = g_ssrc[e + 5], s6 = g_ssrc[e + 6], s7 = g_ssrc[e + 7];
        float w0 = g_dinv[s0], w1 = g_dinv[s1], w2 = g_dinv[s2], w3 = g_dinv[s3];
        float w4 = g_dinv[s4], w5 = g_dinv[s5], w6 = g_dinv[s6], w7 = g_dinv[s7];
        float4 v0 = h4[(size_t)s0 * 128 + t];
        float4 v1 = h4[(size_t)s1 * 128 + t];
        float4 v2 = h4[(size_t)s2 * 128 + t];
        float4 v3 = h4[(size_t)s3 * 128 + t];
        float4 v4 = h4[(size_t)s4 * 128 + t];
        float4 v5 = h4[(size_t)s5 * 128 + t];
        float4 v6 = h4[(size_t)s6 * 128 + t];
        float4 v7 = h4[(size_t)s7 * 128 + t];
        a0.x += v0.x * w0; a0.y += v0.y * w0; a0.z += v0.z * w0; a0.w += v0.w * w0;
        a1.x += v1.x * w1; a1.y += v1.y * w1; a1.z += v1.z * w1; a1.w += v1.w * w1;
        a2.x += v2.x * w2; a2.y += v2.y * w2; a2.z += v2.z * w2; a2.w += v2.w * w2;
        a3.x += v3.x * w3; a3.y += v3.y * w3; a3.z += v3.z * w3; a3.w += v3.w * w3;
        a0.x += v4.x * w4; a0.y += v4.y * w4; a0.z += v4.z * w4; a0.w += v4.w * w4;
        a1.x += v5.x * w5; a1.y += v5.y * w5; a1.z += v5.z * w5; a1.w += v5.w * w5;
        a2.x += v6.x * w6; a2.y += v6.y * w6; a2.z += v6.z * w6; a2.w += v6.w * w6;
        a3.x += v7.x * w7; a3.y += v7.y * w7; a3.z += v7.z * w7; a3.w += v7.w * w7;
    }
    for (; e < end; ++e) {
        int s = g_ssrc[e];
        float w = g_dinv[s];
        float4 v = h4[(size_t)s * 128 + t];
        a0.x += v.x * w; a0.y += v.y * w; a0.z += v.z * w; a0.w += v.w * w;
    }
    float4 acc = make_float4(a0.x + a1.x + a2.x + a3.x, a0.y + a1.y + a2.y + a3.y,
                             a0.z + a1.z + a2.z + a3.z, a0.w + a1.w + a2.w + a3.w);
    float wd = g_dinv[d];
    float w2 = wd * wd;
    float4 sv = h4[(size_t)d * 128 + t];
    float4 bb = ((const float4*)bias)[t];
    float4 r;
    r.x = fmaxf(acc.x * wd + sv.x * w2 + bb.x, 0.f);
    r.y = fmaxf(acc.y * wd + sv.y * w2 + bb.y, 0.f);
    r.z = fmaxf(acc.z * wd + sv.z * w2 + bb.z, 0.f);
    r.w = fmaxf(acc.w * wd + sv.w * w2 + bb.w, 0.f);

    if (OUTS == 2) {
        // fused: write x_hid (for fc), then L2-normalize the row and emit split
        ((float4*)out)[(size_t)d * 128 + t] = r;
        float s = r.x * r.x + r.y * r.y + r.z * r.z + r.w * r.w;
#pragma unroll
        for (int o = 16; o; o >>= 1) s += __shfl_xor_sync(0xffffffffu, s, o);
        if ((t & 31) == 0) red[t >> 5] = s;
        __syncthreads();
        float tot = red[0] + red[1] + red[2] + red[3];
        float inv = (tot > 0.f) ? rsqrtf(tot) : 0.f;
        r.x *= inv; r.y *= inv; r.z *= inv; r.w *= inv;
    }

    // emit bf16 hi/lo split of r (OUTS==1: relu'd row; OUTS==2: normalized row)
    __nv_bfloat16 h0 = __float2bfloat16(r.x), h1 = __float2bfloat16(r.y);
    __nv_bfloat16 h2 = __float2bfloat16(r.z), h3 = __float2bfloat16(r.w);
    __nv_bfloat162* H2 = (__nv_bfloat162*)(OH + (size_t)d * 512 + t * 4);
    H2[0] = __nv_bfloat162(h0, h1);
    H2[1] = __nv_bfloat162(h2, h3);
    __nv_bfloat16 l0 = __float2bfloat16(r.x - __bfloat162float(h0));
    __nv_bfloat16 l1 = __float2bfloat16(r.y - __bfloat162float(h1));
    __nv_bfloat16 l2 = __float2bfloat16(r.z - __bfloat162float(h2));
    __nv_bfloat16 l3 = __float2bfloat16(r.w - __bfloat162float(h3));
    __nv_bfloat162* L2 = (__nv_bfloat162*)(OL + (size_t)d * 512 + t * 4);
    L2[0] = __nv_bfloat162(l0, l1);
    L2[1] = __nv_bfloat162(l2, l3);
}

// ---------------- FC head ----------------
__global__ __launch_bounds__(256) void k_fc(
    const float* __restrict__ X, const float* __restrict__ W,
    const float* __restrict__ bias, float* __restrict__ out)
{
    __shared__ float Xs[32][68];
    __shared__ float Ws[64][NO];
    int tid = threadIdx.x;
    int tx = tid & 63;
    int tg = tid >> 6;
    int row0 = blockIdx.x * 32;
    float acc[8];
#pragma unroll
    for (int i = 0; i < 8; i++) acc[i] = 0.f;

    for (int k0 = 0; k0 < NH; k0 += 64) {
        int xr = tid >> 3, xk = (tid & 7) * 8;
        *(float4*)&Xs[xr][xk]     = *(const float4*)&X[(size_t)(row0 + xr) * NH + k0 + xk];
        *(float4*)&Xs[xr][xk + 4] = *(const float4*)&X[(size_t)(row0 + xr) * NH + k0 + xk + 4];
        int wr = tid >> 2, wc = (tid & 3) * 16;
#pragma unroll
        for (int q = 0; q < 16; q += 4)
            *(float4*)&Ws[wr][wc + q] = *(const float4*)&W[(size_t)(k0 + wr) * NO + wc + q];
        __syncthreads();
#pragma unroll 16
        for (int k = 0; k < 64; k++) {
            float w = Ws[k][tx];
#pragma unroll
            for (int i = 0; i < 8; i++) acc[i] += Xs[tg * 8 + i][k] * w;
        }
        __syncthreads();
    }
#pragma unroll
    for (int i = 0; i < 8; i++) {
        float2 v = make_float2(acc[i] + bias[tx], 0.f);
        asm volatile("st.global.cs.f32 [%0], %1;"
                     :: "l"(&out[(size_t)(row0 + tg * 8 + i) * NO + tx]), "f"(v.x) : "memory");
    }
}

// ---------------- launch ----------------
extern "C" void kernel_launch(void* const* d_in, const int* in_sizes, int n_in,
                              void* d_out, int out_size) {
    const float* x   = (const float*)d_in[0];
    const int*   ei  = (const int*)d_in[1];
    const float* W1  = (const float*)d_in[2];
    const float* b1  = (const float*)d_in[3];
    const float* W2  = (const float*)d_in[4];
    const float* b2  = (const float*)d_in[5];
    const float* fcW = (const float*)d_in[6];
    const float* fcb = (const float*)d_in[7];

    const int* src = ei;
    const int* dst = ei + NEDGE;

    float* outp   = (float*)d_out;
    float* logits = outp;
    float* dis    = outp + (size_t)NNODE * NO;

    float *p1, *p3, *pxh;
    cudaGetSymbolAddress((void**)&p1,  g_buf1);
    cudaGetSymbolAddress((void**)&p3,  g_buf3);
    cudaGetSymbolAddress((void**)&pxh, g_xhid);
    __nv_bfloat16 *ahi, *alo, *whi, *wlo;
    cudaGetSymbolAddress((void**)&ahi, g_Ahi);
    cudaGetSymbolAddress((void**)&alo, g_Alo);
    cudaGetSymbolAddress((void**)&whi, g_Whi);
    cudaGetSymbolAddress((void**)&wlo, g_Wlo);

    cudaFuncSetAttribute(k_mma_gemm<0>, cudaFuncAttributeMaxDynamicSharedMemorySize, SMEM_TOTAL);
    cudaFuncSetAttribute(k_mma_gemm<1>, cudaFuncAttributeMaxDynamicSharedMemorySize, SMEM_TOTAL);

    // CSR build
    k_zero<<<NNODE / 256, 256>>>();
    k_count<<<NEDGE / 256, 256>>>(dst);
    k_scan<<<1, 1024>>>();
    k_fill<<<NEDGE / 256, 256>>>(src, dst);

    dim3 tblk(32, 32);
    dim3 tgrd(16, 16);
    int splitGrid = NNODE * NH / (256 * 4);
    dim3 gconv(NH / 128, NNODE / 128);       // (4, 64)

    // conv1
    k_prepW<<<tgrd, tblk>>>(W1, whi, wlo);
    k_splitF<<<splitGrid, 256>>>(x, ahi, alo);
    k_mma_gemm<0><<<gconv, 256, SMEM_TOTAL>>>(ahi, alo, whi, wlo, p1, NH);
    k_agg<1><<<NNODE, 128>>>(p1, b1, nullptr, ahi, alo);
    // conv2
    k_prepW<<<tgrd, tblk>>>(W2, whi, wlo);
    k_mma_gemm<0><<<gconv, 256, SMEM_TOTAL>>>(ahi, alo, whi, wlo, p3, NH);
    k_agg<2><<<NNODE, 128>>>(p3, b2, pxh, ahi, alo);   // fused agg+relu+norm+split
    // heads
    k_fc<<<NNODE / 32, 256>>>(pxh, fcW, fcb, logits);
    int ntri = (NNODE / 128) * (NNODE / 128 + 1) / 2;   // 2080
    k_mma_gemm<1><<<ntri, 256, SMEM_TOTAL>>>(ahi, alo, ahi, alo, dis, NNODE);
}

// round 16
// speedup vs baseline: 1.0186x; 1.0186x over previous
#include <cuda_runtime.h>
#include <cuda_bf16.h>
#include <cstdint>
#include <math.h>

#define NNODE 8192
#define NEDGE 262144
#define KF    512
#define NH    512
#define NO    64

#define NCHUNK 24              // K=1536 bf16 in chunks of 64
#define NSTAGE 3
#define STAGE_BYTES 32768      // A 16KB + B 16KB per stage
#define SMEM_TOTAL (NSTAGE * STAGE_BYTES)   // 98304

// ---------------- scratch ----------------
__device__ float g_buf1[NNODE * NH];
__device__ float g_buf3[NNODE * NH];
__device__ float g_xhid[NNODE * NH];
__device__ float g_dinv[NNODE];
__device__ int   g_cnt [NNODE];
__device__ int   g_off [NNODE + 1];
__device__ int   g_cur [NNODE];
__device__ int   g_ssrc[NEDGE];
__device__ __nv_bfloat16 g_Ahi[NNODE * NH];
__device__ __nv_bfloat16 g_Alo[NNODE * NH];
__device__ __nv_bfloat16 g_Whi[NH * NH];
__device__ __nv_bfloat16 g_Wlo[NH * NH];

// ---------------- PTX helpers ----------------
__device__ __forceinline__ uint32_t smem_u32(const void* p) {
    uint32_t a;
    asm("{ .reg .u64 t; cvta.to.shared.u64 t, %1; cvt.u32.u64 %0, t; }" : "=r"(a) : "l"(p));
    return a;
}
__device__ __forceinline__ void cp_async16(uint32_t saddr, const void* g) {
    asm volatile("cp.async.cg.shared.global [%0], [%1], 16;" :: "r"(saddr), "l"(g) : "memory");
}
__device__ __forceinline__ void cp_commit() {
    asm volatile("cp.async.commit_group;" ::: "memory");
}
template <int N> __device__ __forceinline__ void cp_wait() {
    asm volatile("cp.async.wait_group %0;" :: "n"(N) : "memory");
}
__device__ __forceinline__ void ldsm_x4(uint32_t& r0, uint32_t& r1, uint32_t& r2, uint32_t& r3,
                                        uint32_t a) {
    asm volatile("ldmatrix.sync.aligned.m8n8.x4.shared.b16 {%0,%1,%2,%3}, [%4];"
                 : "=r"(r0), "=r"(r1), "=r"(r2), "=r"(r3) : "r"(a));
}
__device__ __forceinline__ void mma_bf16(float* d, const uint32_t* a, const uint32_t* b) {
    asm volatile(
        "mma.sync.aligned.m16n8k16.row.col.f32.bf16.bf16.f32 "
        "{%0,%1,%2,%3}, {%4,%5,%6,%7}, {%8,%9}, {%0,%1,%2,%3};"
        : "+f"(d[0]), "+f"(d[1]), "+f"(d[2]), "+f"(d[3])
        : "r"(a[0]), "r"(a[1]), "r"(a[2]), "r"(a[3]), "r"(b[0]), "r"(b[1]));
}
__device__ __forceinline__ void stg_cs_64(float* p, float a, float b) {
    float2 v = make_float2(a, b);
    asm volatile("st.global.cs.v2.f32 [%0], {%1, %2};" :: "l"(p), "f"(v.x), "f"(v.y) : "memory");
}
__device__ __forceinline__ void stg_cs_128(float* p, float4 v) {
    asm volatile("st.global.cs.v4.f32 [%0], {%1, %2, %3, %4};"
                 :: "l"(p), "f"(v.x), "f"(v.y), "f"(v.z), "f"(v.w) : "memory");
}

// ---------------- CSR build (vectorized: 4 edges/thread) ----------------
__global__ void k_zero() {
    int i = blockIdx.x * blockDim.x + threadIdx.x;
    if (i < NNODE) g_cnt[i] = 0;
}
__global__ void k_count(const int* __restrict__ dst) {
    int i = (blockIdx.x * blockDim.x + threadIdx.x) * 4;
    int4 d = *(const int4*)(dst + i);
    atomicAdd(&g_cnt[d.x], 1);
    atomicAdd(&g_cnt[d.y], 1);
    atomicAdd(&g_cnt[d.z], 1);
    atomicAdd(&g_cnt[d.w], 1);
}
__global__ void k_scan() {
    __shared__ int ssum[1024];
    int t = threadIdx.x;
    int base = t * 8;
    int c[8];
    int s = 0;
#pragma unroll
    for (int i = 0; i < 8; i++) { c[i] = g_cnt[base + i]; s += c[i]; }
    ssum[t] = s;
    __syncthreads();
    for (int off = 1; off < 1024; off <<= 1) {
        int v = (t >= off) ? ssum[t - off] : 0;
        __syncthreads();
        ssum[t] += v;
        __syncthreads();
    }
    int excl = ssum[t] - s;
#pragma unroll
    for (int i = 0; i < 8; i++) {
        g_off[base + i] = excl;
        g_cur[base + i] = excl;
        g_dinv[base + i] = rsqrtf((float)c[i] + 1.0f);
        excl += c[i];
    }
    if (t == 1023) g_off[NNODE] = ssum[1023];
}
__global__ void k_fill(const int* __restrict__ src, const int* __restrict__ dst) {
    int i = (blockIdx.x * blockDim.x + threadIdx.x) * 4;
    int4 d = *(const int4*)(dst + i);
    int4 s = *(const int4*)(src + i);
    int p0 = atomicAdd(&g_cur[d.x], 1);
    int p1 = atomicAdd(&g_cur[d.y], 1);
    int p2 = atomicAdd(&g_cur[d.z], 1);
    int p3 = atomicAdd(&g_cur[d.w], 1);
    g_ssrc[p0] = s.x;
    g_ssrc[p1] = s.y;
    g_ssrc[p2] = s.z;
    g_ssrc[p3] = s.w;
}

// ---------------- split fp32 -> bf16 hi/lo (for x only) ----------------
__global__ void k_splitF(const float* __restrict__ X,
                         __nv_bfloat16* __restrict__ H, __nv_bfloat16* __restrict__ L) {
    int i = (blockIdx.x * blockDim.x + threadIdx.x) * 4;
    float4 v = *(const float4*)(X + i);
    __nv_bfloat16 h0 = __float2bfloat16(v.x), h1 = __float2bfloat16(v.y);
    __nv_bfloat16 h2 = __float2bfloat16(v.z), h3 = __float2bfloat16(v.w);
    __nv_bfloat162* H2 = (__nv_bfloat162*)(H + i);
    H2[0] = __nv_bfloat162(h0, h1);
    H2[1] = __nv_bfloat162(h2, h3);
    __nv_bfloat16 l0 = __float2bfloat16(v.x - __bfloat162float(h0));
    __nv_bfloat16 l1 = __float2bfloat16(v.y - __bfloat162float(h1));
    __nv_bfloat16 l2 = __float2bfloat16(v.z - __bfloat162float(h2));
    __nv_bfloat16 l3 = __float2bfloat16(v.w - __bfloat162float(h3));
    __nv_bfloat162* L2 = (__nv_bfloat162*)(L + i);
    L2[0] = __nv_bfloat162(l0, l1);
    L2[1] = __nv_bfloat162(l2, l3);
}

// ---------------- transpose + split W[512,512] ----------------
__global__ void k_prepW(const float* __restrict__ W,
                        __nv_bfloat16* __restrict__ TH, __nv_bfloat16* __restrict__ TL) {
    __shared__ float t[32][33];
    int tx = threadIdx.x, ty = threadIdx.y;
    int k0 = blockIdx.x * 32, n0 = blockIdx.y * 32;
    t[ty][tx] = W[(size_t)(k0 + ty) * NH + n0 + tx];
    __syncthreads();
    float v = t[tx][ty];
    __nv_bfloat16 h = __float2bfloat16(v);
    __nv_bfloat16 l = __float2bfloat16(v - __bfloat162float(h));
    TH[(size_t)(n0 + ty) * NH + k0 + tx] = h;
    TL[(size_t)(n0 + ty) * NH + k0 + tx] = l;
}

// ---------------- HMMA GEMM: 128x128 tile, 256 thr, 8 warps, 3-stage ----------------
// MODE 0: C = A @ B^T plain (2D grid). MODE 1: symmetric dis, triangular 1D grid,
//         evict-first (.cs) output stores.
__device__ __forceinline__ void load_chunk(
    const __nv_bfloat16* __restrict__ Asrc, const __nv_bfloat16* __restrict__ Bsrc,
    int rowbA, int rowbB, int kbyte, uint32_t sA, int tid)
{
#pragma unroll
    for (int j = 0; j < 4; j++) {
        int u = tid + 256 * j;               // 0..1023
        int r = u >> 3, q = u & 7;
        int off = r * 128 + ((q * 16) ^ ((r & 7) * 16));
        cp_async16(sA + off,         (const char*)Asrc + (size_t)(rowbA + r) * 1024 + kbyte + q * 16);
        cp_async16(sA + 16384 + off, (const char*)Bsrc + (size_t)(rowbB + r) * 1024 + kbyte + q * 16);
    }
}

template <int MODE>
__global__ __launch_bounds__(256, 2) void k_mma_gemm(
    const __nv_bfloat16* __restrict__ Ahi, const __nv_bfloat16* __restrict__ Alo,
    const __nv_bfloat16* __restrict__ Bhi, const __nv_bfloat16* __restrict__ Blo,
    float* __restrict__ C, int ldc)
{
    int bx, by;
    if (MODE == 1) {
        // triangular unrank: id = bx*(bx+1)/2 + by, by <= bx
        int id = blockIdx.x;
        int b = (int)((sqrtf(8.0f * (float)id + 1.0f) - 1.0f) * 0.5f);
        while ((b + 1) * (b + 2) / 2 <= id) ++b;
        while (b * (b + 1) / 2 > id) --b;
        bx = b;
        by = id - b * (b + 1) / 2;
    } else {
        bx = blockIdx.x;
        by = blockIdx.y;
    }

    extern __shared__ char smem[];
    uint32_t sb = smem_u32(smem);
    int tid = threadIdx.x;
    int lane = tid & 31, wid = tid >> 5;
    int wm = wid & 1, wn = wid >> 1;         // warp tile: rows wm*64, cols wn*32

    int rowbA = by * 128;
    int rowbB = bx * 128;

    float acc[4][4][4];
#pragma unroll
    for (int mt = 0; mt < 4; mt++)
#pragma unroll
        for (int nt = 0; nt < 4; nt++)
#pragma unroll
            for (int e = 0; e < 4; e++) acc[mt][nt][e] = 0.f;

    int arow = wm * 64 + (lane & 15);
    int akb  = (lane >> 4) * 16;
    int brow = wn * 32 + ((lane >> 4) << 3) + (lane & 7);  // x4: lanes 0-15 n0-7, 16-31 n8-15
    int bkb  = ((lane >> 3) & 1) * 16;

    // prologue: 2 chunks in flight
    load_chunk(Ahi, Bhi, rowbA, rowbB, 0, sb, tid);
    cp_commit();
    load_chunk(Ahi, Bhi, rowbA, rowbB, 128, sb + STAGE_BYTES, tid);
    cp_commit();

    for (int c = 0; c < NCHUNK; c++) {
        if (c < NCHUNK - 1) cp_wait<1>();
        else                cp_wait<0>();
        __syncthreads();
        if (c + 2 < NCHUNK) {
            int cn = c + 2;
            int part = cn >> 3;
            const __nv_bfloat16* As = (part == 1) ? Alo : Ahi;
            const __nv_bfloat16* Bs = (part == 2) ? Blo : Bhi;
            load_chunk(As, Bs, rowbA, rowbB, (cn & 7) * 128, sb + (cn % NSTAGE) * STAGE_BYTES, tid);
            cp_commit();
        }

        uint32_t stA = sb + (c % NSTAGE) * STAGE_BYTES;
        uint32_t stB = stA + 16384;
#pragma unroll
        for (int kt = 0; kt < 4; kt++) {
            uint32_t af[4][4], bf[4][2];
#pragma unroll
            for (int mt = 0; mt < 4; mt++) {
                int r = arow + mt * 16;
                int kb = kt * 32 + akb;
                uint32_t ad = stA + r * 128 + (kb ^ ((r & 7) * 16));
                ldsm_x4(af[mt][0], af[mt][1], af[mt][2], af[mt][3], ad);
            }
#pragma unroll
            for (int ntp = 0; ntp < 2; ntp++) {
                int r = brow + ntp * 16;
                int kb = kt * 32 + bkb;
                uint32_t bd = stB + r * 128 + (kb ^ ((r & 7) * 16));
                ldsm_x4(bf[2 * ntp][0], bf[2 * ntp][1], bf[2 * ntp + 1][0], bf[2 * ntp + 1][1], bd);
            }
#pragma unroll
            for (int mt = 0; mt < 4; mt++)
#pragma unroll
                for (int nt = 0; nt < 4; nt++)
                    mma_bf16(acc[mt][nt], af[mt], bf[nt]);
        }
    }

    // ---------------- epilogue ----------------
    int lr0 = wm * 64 + (lane >> 2);
    int lc0 = wn * 32 + (lane & 3) * 2;
    float* T = (float*)smem;                 // [128][132] transpose buffer (MODE 1)
    if (MODE == 1) __syncthreads();

#pragma unroll
    for (int mt = 0; mt < 4; mt++) {
#pragma unroll
        for (int nt = 0; nt < 4; nt++) {
            float* a = acc[mt][nt];
            int lr = lr0 + mt * 16;
            int lc = lc0 + nt * 8;
            if (MODE == 1 && bx == by) {
                if (lr == lc) a[0] = 0.f;
                if (lr == lc + 1) a[1] = 0.f;
                if (lr + 8 == lc) a[2] = 0.f;
                if (lr + 8 == lc + 1) a[3] = 0.f;
            }
            size_t g0 = (size_t)(by * 128 + lr) * ldc + bx * 128 + lc;
            if (MODE == 1) {
                stg_cs_64(&C[g0], a[0], a[1]);
                stg_cs_64(&C[g0 + 8 * ldc], a[2], a[3]);
            } else {
                *(float2*)&C[g0] = make_float2(a[0], a[1]);
                *(float2*)&C[g0 + 8 * ldc] = make_float2(a[2], a[3]);
            }
            if (MODE == 1 && bx != by) {
                T[lc * 132 + lr] = a[0];
                T[(lc + 1) * 132 + lr] = a[1];
                T[lc * 132 + lr + 8] = a[2];
                T[(lc + 1) * 132 + lr + 8] = a[3];
            }
        }
    }

    if (MODE == 1 && bx != by) {
        __syncthreads();
        // coalesced mirror write-out: each warp writes one contiguous 512B row
        // segment per iteration (8 warps x 16 iters = 128 rows)
#pragma unroll
        for (int it = 0; it < 16; it++) {
            int mrow = wid + it * 8;
            const float* Tr = &T[mrow * 132 + lane * 4];
            float4 v = make_float4(Tr[0], Tr[1], Tr[2], Tr[3]);
            stg_cs_128(&C[(size_t)(bx * 128 + mrow) * ldc + by * 128 + lane * 4], v);
        }
    }
}

// ---------------- GCN aggregation (unroll-4) ----------------
// OUTS=1: conv1 -> relu -> bf16 hi/lo split (conv2 input)
// OUTS=2: conv2 -> relu -> pxh (fp32, for fc) + L2-normalized bf16 hi/lo split (dis input)
template <int OUTS>
__global__ __launch_bounds__(128) void k_agg(
    const float* __restrict__ h, const float* __restrict__ bias,
    float* __restrict__ out, __nv_bfloat16* __restrict__ OH, __nv_bfloat16* __restrict__ OL)
{
    __shared__ float red[4];
    int d = blockIdx.x;
    int t = threadIdx.x;
    const float4* h4 = (const float4*)h;
    float4 acc0 = make_float4(0.f, 0.f, 0.f, 0.f);
    float4 acc1 = make_float4(0.f, 0.f, 0.f, 0.f);
    int e = g_off[d], end = g_off[d + 1];
    for (; e + 4 <= end; e += 4) {
        int s0 = g_ssrc[e], s1 = g_ssrc[e + 1], s2 = g_ssrc[e + 2], s3 = g_ssrc[e + 3];
        float w0 = g_dinv[s0], w1 = g_dinv[s1], w2 = g_dinv[s2], w3 = g_dinv[s3];
        float4 v0 = h4[(size_t)s0 * 128 + t];
        float4 v1 = h4[(size_t)s1 * 128 + t];
        float4 v2 = h4[(size_t)s2 * 128 + t];
        float4 v3 = h4[(size_t)s3 * 128 + t];
        acc0.x += v0.x * w0; acc0.y += v0.y * w0; acc0.z += v0.z * w0; acc0.w += v0.w * w0;
        acc1.x += v1.x * w1; acc1.y += v1.y * w1; acc1.z += v1.z * w1; acc1.w += v1.w * w1;
        acc0.x += v2.x * w2; acc0.y += v2.y * w2; acc0.z += v2.z * w2; acc0.w += v2.w * w2;
        acc1.x += v3.x * w3; acc1.y += v3.y * w3; acc1.z += v3.z * w3; acc1.w += v3.w * w3;
    }
    for (; e < end; ++e) {
        int s = g_ssrc[e];
        float w = g_dinv[s];
        float4 v = h4[(size_t)s * 128 + t];
        acc0.x += v.x * w; acc0.y += v.y * w; acc0.z += v.z * w; acc0.w += v.w * w;
    }
    float4 acc = make_float4(acc0.x + acc1.x, acc0.y + acc1.y, acc0.z + acc1.z, acc0.w + acc1.w);
    float wd = g_dinv[d];
    float w2 = wd * wd;
    float4 sv = h4[(size_t)d * 128 + t];
    float4 bb = ((const float4*)bias)[t];
    float4 r;
    r.x = fmaxf(acc.x * wd + sv.x * w2 + bb.x, 0.f);
    r.y = fmaxf(acc.y * wd + sv.y * w2 + bb.y, 0.f);
    r.z = fmaxf(acc.z * wd + sv.z * w2 + bb.z, 0.f);
    r.w = fmaxf(acc.w * wd + sv.w * w2 + bb.w, 0.f);

    if (OUTS == 2) {
        // fused: write x_hid (for fc), then L2-normalize the row and emit split
        ((float4*)out)[(size_t)d * 128 + t] = r;
        float s = r.x * r.x + r.y * r.y + r.z * r.z + r.w * r.w;
#pragma unroll
        for (int o = 16; o; o >>= 1) s += __shfl_xor_sync(0xffffffffu, s, o);
        if ((t & 31) == 0) red[t >> 5] = s;
        __syncthreads();
        float tot = red[0] + red[1] + red[2] + red[3];
        float inv = (tot > 0.f) ? rsqrtf(tot) : 0.f;
        r.x *= inv; r.y *= inv; r.z *= inv; r.w *= inv;
    }

    // emit bf16 hi/lo split of r (OUTS==1: relu'd row; OUTS==2: normalized row)
    __nv_bfloat16 h0 = __float2bfloat16(r.x), h1 = __float2bfloat16(r.y);
    __nv_bfloat16 h2 = __float2bfloat16(r.z), h3 = __float2bfloat16(r.w);
    __nv_bfloat162* H2 = (__nv_bfloat162*)(OH + (size_t)d * 512 + t * 4);
    H2[0] = __nv_bfloat162(h0, h1);
    H2[1] = __nv_bfloat162(h2, h3);
    __nv_bfloat16 l0 = __float2bfloat16(r.x - __bfloat162float(h0));
    __nv_bfloat16 l1 = __float2bfloat16(r.y - __bfloat162float(h1));
    __nv_bfloat16 l2 = __float2bfloat16(r.z - __bfloat162float(h2));
    __nv_bfloat16 l3 = __float2bfloat16(r.w - __bfloat162float(h3));
    __nv_bfloat162* L2 = (__nv_bfloat162*)(OL + (size_t)d * 512 + t * 4);
    L2[0] = __nv_bfloat162(l0, l1);
    L2[1] = __nv_bfloat162(l2, l3);
}

// ---------------- FC head ----------------
__global__ __launch_bounds__(256) void k_fc(
    const float* __restrict__ X, const float* __restrict__ W,
    const float* __restrict__ bias, float* __restrict__ out)
{
    __shared__ float Xs[32][68];
    __shared__ float Ws[64][NO];
    int tid = threadIdx.x;
    int tx = tid & 63;
    int tg = tid >> 6;
    int row0 = blockIdx.x * 32;
    float acc[8];
#pragma unroll
    for (int i = 0; i < 8; i++) acc[i] = 0.f;

    for (int k0 = 0; k0 < NH; k0 += 64) {
        int xr = tid >> 3, xk = (tid & 7) * 8;
        *(float4*)&Xs[xr][xk]     = *(const float4*)&X[(size_t)(row0 + xr) * NH + k0 + xk];
        *(float4*)&Xs[xr][xk + 4] = *(const float4*)&X[(size_t)(row0 + xr) * NH + k0 + xk + 4];
        int wr = tid >> 2, wc = (tid & 3) * 16;
#pragma unroll
        for (int q = 0; q < 16; q += 4)
            *(float4*)&Ws[wr][wc + q] = *(const float4*)&W[(size_t)(k0 + wr) * NO + wc + q];
        __syncthreads();
#pragma unroll 16
        for (int k = 0; k < 64; k++) {
            float w = Ws[k][tx];
#pragma unroll
            for (int i = 0; i < 8; i++) acc[i] += Xs[tg * 8 + i][k] * w;
        }
        __syncthreads();
    }
#pragma unroll
    for (int i = 0; i < 8; i++)
        out[(size_t)(row0 + tg * 8 + i) * NO + tx] = acc[i] + bias[tx];
}

// ---------------- launch ----------------
extern "C" void kernel_launch(void* const* d_in, const int* in_sizes, int n_in,
                              void* d_out, int out_size) {
    const float* x   = (const float*)d_in[0];
    const int*   ei  = (const int*)d_in[1];
    const float* W1  = (const float*)d_in[2];
    const float* b1  = (const float*)d_in[3];
    const float* W2  = (const float*)d_in[4];
    const float* b2  = (const float*)d_in[5];
    const float* fcW = (const float*)d_in[6];
    const float* fcb = (const float*)d_in[7];

    const int* src = ei;
    const int* dst = ei + NEDGE;

    float* outp   = (float*)d_out;
    float* logits = outp;
    float* dis    = outp + (size_t)NNODE * NO;

    float *p1, *p3, *pxh;
    cudaGetSymbolAddress((void**)&p1,  g_buf1);
    cudaGetSymbolAddress((void**)&p3,  g_buf3);
    cudaGetSymbolAddress((void**)&pxh, g_xhid);
    __nv_bfloat16 *ahi, *alo, *whi, *wlo;
    cudaGetSymbolAddress((void**)&ahi, g_Ahi);
    cudaGetSymbolAddress((void**)&alo, g_Alo);
    cudaGetSymbolAddress((void**)&whi, g_Whi);
    cudaGetSymbolAddress((void**)&wlo, g_Wlo);

    cudaFuncSetAttribute(k_mma_gemm<0>, cudaFuncAttributeMaxDynamicSharedMemorySize, SMEM_TOTAL);
    cudaFuncSetAttribute(k_mma_gemm<1>, cudaFuncAttributeMaxDynamicSharedMemorySize, SMEM_TOTAL);

    // CSR build
    k_zero<<<NNODE / 256, 256>>>();
    k_count<<<NEDGE / 1024, 256>>>(dst);
    k_scan<<<1, 1024>>>();
    k_fill<<<NEDGE / 1024, 256>>>(src, dst);

    dim3 tblk(32, 32);
    dim3 tgrd(16, 16);
    int splitGrid = NNODE * NH / (256 * 4);
    dim3 gconv(NH / 128, NNODE / 128);       // (4, 64)

    // conv1
    k_prepW<<<tgrd, tblk>>>(W1, whi, wlo);
    k_splitF<<<splitGrid, 256>>>(x, ahi, alo);
    k_mma_gemm<0><<<gconv, 256, SMEM_TOTAL>>>(ahi, alo, whi, wlo, p1, NH);
    k_agg<1><<<NNODE, 128>>>(p1, b1, nullptr, ahi, alo);
    // conv2
    k_prepW<<<tgrd, tblk>>>(W2, whi, wlo);
    k_mma_gemm<0><<<gconv, 256, SMEM_TOTAL>>>(ahi, alo, whi, wlo, p3, NH);
    k_agg<2><<<NNODE, 128>>>(p3, b2, pxh, ahi, alo);   // fused agg+relu+norm+split
    // heads
    k_fc<<<NNODE / 32, 256>>>(pxh, fcW, fcb, logits);
    int ntri = (NNODE / 128) * (NNODE / 128 + 1) / 2;   // 2080
    k_mma_gemm<1><<<ntri, 256, SMEM_TOTAL>>>(ahi, alo, ahi, alo, dis, NNODE);
}

// round 17
// speedup vs baseline: 1.0270x; 1.0082x over previous
#include <cuda_runtime.h>
#include <cuda_bf16.h>
#include <cstdint>
#include <math.h>

#define NNODE 8192
#define NEDGE 262144
#define KF    512
#define NH    512
#define NO    64

#define NCHUNK 24              // K=1536 bf16 in chunks of 64
#define NSTAGE 3
#define STAGE_BYTES 32768      // A 16KB + B 16KB per stage
#define SMEM_TOTAL (NSTAGE * STAGE_BYTES)   // 98304
#define NTRI 2080              // 64*65/2 triangular tiles
#define NFCB 256               // fc blocks appended to dis grid

// ---------------- scratch ----------------
__device__ float g_buf1[NNODE * NH];
__device__ float g_buf3[NNODE * NH];
__device__ float g_xhid[NNODE * NH];
__device__ float g_dinv[NNODE];
__device__ int   g_cnt [NNODE];
__device__ int   g_off [NNODE + 1];
__device__ int   g_cur [NNODE];
__device__ int   g_ssrc[NEDGE];
__device__ __nv_bfloat16 g_Ahi[NNODE * NH];
__device__ __nv_bfloat16 g_Alo[NNODE * NH];
__device__ __nv_bfloat16 g_Whi[NH * NH];
__device__ __nv_bfloat16 g_Wlo[NH * NH];

// ---------------- PTX helpers ----------------
__device__ __forceinline__ uint32_t smem_u32(const void* p) {
    uint32_t a;
    asm("{ .reg .u64 t; cvta.to.shared.u64 t, %1; cvt.u32.u64 %0, t; }" : "=r"(a) : "l"(p));
    return a;
}
__device__ __forceinline__ void cp_async16(uint32_t saddr, const void* g) {
    asm volatile("cp.async.cg.shared.global [%0], [%1], 16;" :: "r"(saddr), "l"(g) : "memory");
}
__device__ __forceinline__ void cp_commit() {
    asm volatile("cp.async.commit_group;" ::: "memory");
}
template <int N> __device__ __forceinline__ void cp_wait() {
    asm volatile("cp.async.wait_group %0;" :: "n"(N) : "memory");
}
__device__ __forceinline__ void ldsm_x4(uint32_t& r0, uint32_t& r1, uint32_t& r2, uint32_t& r3,
                                        uint32_t a) {
    asm volatile("ldmatrix.sync.aligned.m8n8.x4.shared.b16 {%0,%1,%2,%3}, [%4];"
                 : "=r"(r0), "=r"(r1), "=r"(r2), "=r"(r3) : "r"(a));
}
__device__ __forceinline__ void mma_bf16(float* d, const uint32_t* a, const uint32_t* b) {
    asm volatile(
        "mma.sync.aligned.m16n8k16.row.col.f32.bf16.bf16.f32 "
        "{%0,%1,%2,%3}, {%4,%5,%6,%7}, {%8,%9}, {%0,%1,%2,%3};"
        : "+f"(d[0]), "+f"(d[1]), "+f"(d[2]), "+f"(d[3])
        : "r"(a[0]), "r"(a[1]), "r"(a[2]), "r"(a[3]), "r"(b[0]), "r"(b[1]));
}
__device__ __forceinline__ void stg_cs_64(float* p, float a, float b) {
    float2 v = make_float2(a, b);
    asm volatile("st.global.cs.v2.f32 [%0], {%1, %2};" :: "l"(p), "f"(v.x), "f"(v.y) : "memory");
}
__device__ __forceinline__ void stg_cs_128(float* p, float4 v) {
    asm volatile("st.global.cs.v4.f32 [%0], {%1, %2, %3, %4};"
                 :: "l"(p), "f"(v.x), "f"(v.y), "f"(v.z), "f"(v.w) : "memory");
}

// ---------------- CSR build (vectorized: 4 edges/thread) ----------------
__global__ void k_zero() {
    int i = blockIdx.x * blockDim.x + threadIdx.x;
    if (i < NNODE) g_cnt[i] = 0;
}
__global__ void k_count(const int* __restrict__ dst) {
    int i = (blockIdx.x * blockDim.x + threadIdx.x) * 4;
    int4 d = *(const int4*)(dst + i);
    atomicAdd(&g_cnt[d.x], 1);
    atomicAdd(&g_cnt[d.y], 1);
    atomicAdd(&g_cnt[d.z], 1);
    atomicAdd(&g_cnt[d.w], 1);
}
__global__ void k_scan() {
    __shared__ int ssum[1024];
    int t = threadIdx.x;
    int base = t * 8;
    int c[8];
    int s = 0;
#pragma unroll
    for (int i = 0; i < 8; i++) { c[i] = g_cnt[base + i]; s += c[i]; }
    ssum[t] = s;
    __syncthreads();
    for (int off = 1; off < 1024; off <<= 1) {
        int v = (t >= off) ? ssum[t - off] : 0;
        __syncthreads();
        ssum[t] += v;
        __syncthreads();
    }
    int excl = ssum[t] - s;
#pragma unroll
    for (int i = 0; i < 8; i++) {
        g_off[base + i] = excl;
        g_cur[base + i] = excl;
        g_dinv[base + i] = rsqrtf((float)c[i] + 1.0f);
        excl += c[i];
    }
    if (t == 1023) g_off[NNODE] = ssum[1023];
}
__global__ void k_fill(const int* __restrict__ src, const int* __restrict__ dst) {
    int i = (blockIdx.x * blockDim.x + threadIdx.x) * 4;
    int4 d = *(const int4*)(dst + i);
    int4 s = *(const int4*)(src + i);
    int p0 = atomicAdd(&g_cur[d.x], 1);
    int p1 = atomicAdd(&g_cur[d.y], 1);
    int p2 = atomicAdd(&g_cur[d.z], 1);
    int p3 = atomicAdd(&g_cur[d.w], 1);
    g_ssrc[p0] = s.x;
    g_ssrc[p1] = s.y;
    g_ssrc[p2] = s.z;
    g_ssrc[p3] = s.w;
}

// ---------------- split fp32 -> bf16 hi/lo (for x only) ----------------
__global__ void k_splitF(const float* __restrict__ X,
                         __nv_bfloat16* __restrict__ H, __nv_bfloat16* __restrict__ L) {
    int i = (blockIdx.x * blockDim.x + threadIdx.x) * 4;
    float4 v = *(const float4*)(X + i);
    __nv_bfloat16 h0 = __float2bfloat16(v.x), h1 = __float2bfloat16(v.y);
    __nv_bfloat16 h2 = __float2bfloat16(v.z), h3 = __float2bfloat16(v.w);
    __nv_bfloat162* H2 = (__nv_bfloat162*)(H + i);
    H2[0] = __nv_bfloat162(h0, h1);
    H2[1] = __nv_bfloat162(h2, h3);
    __nv_bfloat16 l0 = __float2bfloat16(v.x - __bfloat162float(h0));
    __nv_bfloat16 l1 = __float2bfloat16(v.y - __bfloat162float(h1));
    __nv_bfloat16 l2 = __float2bfloat16(v.z - __bfloat162float(h2));
    __nv_bfloat16 l3 = __float2bfloat16(v.w - __bfloat162float(h3));
    __nv_bfloat162* L2 = (__nv_bfloat162*)(L + i);
    L2[0] = __nv_bfloat162(l0, l1);
    L2[1] = __nv_bfloat162(l2, l3);
}

// ---------------- transpose + split W[512,512] ----------------
__global__ void k_prepW(const float* __restrict__ W,
                        __nv_bfloat16* __restrict__ TH, __nv_bfloat16* __restrict__ TL) {
    __shared__ float t[32][33];
    int tx = threadIdx.x, ty = threadIdx.y;
    int k0 = blockIdx.x * 32, n0 = blockIdx.y * 32;
    t[ty][tx] = W[(size_t)(k0 + ty) * NH + n0 + tx];
    __syncthreads();
    float v = t[tx][ty];
    __nv_bfloat16 h = __float2bfloat16(v);
    __nv_bfloat16 l = __float2bfloat16(v - __bfloat162float(h));
    TH[(size_t)(n0 + ty) * NH + k0 + tx] = h;
    TL[(size_t)(n0 + ty) * NH + k0 + tx] = l;
}

// ---------------- fc block body (runs inside dis kernel's tail blocks) ----------------
__device__ void fc_block(const float* __restrict__ X, const float* __restrict__ W,
                         const float* __restrict__ bias, float* __restrict__ out,
                         char* smem, int blk)
{
    float (*Xs)[68] = (float(*)[68])smem;                    // 32x68 floats = 8704B
    float (*Ws)[NO] = (float(*)[NO])(smem + 32 * 68 * 4);    // 64x64 floats = 16KB
    int tid = threadIdx.x;
    int tx = tid & 63;
    int tg = tid >> 6;
    int row0 = blk * 32;
    float acc[8];
#pragma unroll
    for (int i = 0; i < 8; i++) acc[i] = 0.f;

    for (int k0 = 0; k0 < NH; k0 += 64) {
        int xr = tid >> 3, xk = (tid & 7) * 8;
        *(float4*)&Xs[xr][xk]     = *(const float4*)&X[(size_t)(row0 + xr) * NH + k0 + xk];
        *(float4*)&Xs[xr][xk + 4] = *(const float4*)&X[(size_t)(row0 + xr) * NH + k0 + xk + 4];
        int wr = tid >> 2, wc = (tid & 3) * 16;
#pragma unroll
        for (int q = 0; q < 16; q += 4)
            *(float4*)&Ws[wr][wc + q] = *(const float4*)&W[(size_t)(k0 + wr) * NO + wc + q];
        __syncthreads();
#pragma unroll 16
        for (int k = 0; k < 64; k++) {
            float w = Ws[k][tx];
#pragma unroll
            for (int i = 0; i < 8; i++) acc[i] += Xs[tg * 8 + i][k] * w;
        }
        __syncthreads();
    }
#pragma unroll
    for (int i = 0; i < 8; i++)
        out[(size_t)(row0 + tg * 8 + i) * NO + tx] = acc[i] + bias[tx];
}

// ---------------- HMMA GEMM: 128x128 tile, 256 thr, 8 warps, 3-stage ----------------
// MODE 0: C = A @ B^T plain (2D grid). MODE 1: symmetric dis, triangular 1D grid,
//         .cs output stores; blocks >= NTRI run the fc head instead.
__device__ __forceinline__ void load_chunk(
    const __nv_bfloat16* __restrict__ Asrc, const __nv_bfloat16* __restrict__ Bsrc,
    int rowbA, int rowbB, int kbyte, uint32_t sA, int tid)
{
#pragma unroll
    for (int j = 0; j < 4; j++) {
        int u = tid + 256 * j;               // 0..1023
        int r = u >> 3, q = u & 7;
        int off = r * 128 + ((q * 16) ^ ((r & 7) * 16));
        cp_async16(sA + off,         (const char*)Asrc + (size_t)(rowbA + r) * 1024 + kbyte + q * 16);
        cp_async16(sA + 16384 + off, (const char*)Bsrc + (size_t)(rowbB + r) * 1024 + kbyte + q * 16);
    }
}

template <int MODE>
__global__ __launch_bounds__(256, 2) void k_mma_gemm(
    const __nv_bfloat16* __restrict__ Ahi, const __nv_bfloat16* __restrict__ Alo,
    const __nv_bfloat16* __restrict__ Bhi, const __nv_bfloat16* __restrict__ Blo,
    float* __restrict__ C, int ldc,
    const float* __restrict__ fcX, const float* __restrict__ fcW,
    const float* __restrict__ fcb, float* __restrict__ fcOut)
{
    extern __shared__ char smem[];
    int bx, by;
    if (MODE == 1) {
        int id = blockIdx.x;
        if (id >= NTRI) {                    // fc tail blocks
            fc_block(fcX, fcW, fcb, fcOut, smem, id - NTRI);
            return;
        }
        // triangular unrank: id = bx*(bx+1)/2 + by, by <= bx
        int b = (int)((sqrtf(8.0f * (float)id + 1.0f) - 1.0f) * 0.5f);
        while ((b + 1) * (b + 2) / 2 <= id) ++b;
        while (b * (b + 1) / 2 > id) --b;
        bx = b;
        by = id - b * (b + 1) / 2;
    } else {
        bx = blockIdx.x;
        by = blockIdx.y;
    }

    uint32_t sb = smem_u32(smem);
    int tid = threadIdx.x;
    int lane = tid & 31, wid = tid >> 5;
    int wm = wid & 1, wn = wid >> 1;         // warp tile: rows wm*64, cols wn*32

    int rowbA = by * 128;
    int rowbB = bx * 128;

    float acc[4][4][4];
#pragma unroll
    for (int mt = 0; mt < 4; mt++)
#pragma unroll
        for (int nt = 0; nt < 4; nt++)
#pragma unroll
            for (int e = 0; e < 4; e++) acc[mt][nt][e] = 0.f;

    int arow = wm * 64 + (lane & 15);
    int akb  = (lane >> 4) * 16;
    int brow = wn * 32 + ((lane >> 4) << 3) + (lane & 7);  // x4: lanes 0-15 n0-7, 16-31 n8-15
    int bkb  = ((lane >> 3) & 1) * 16;

    // prologue: 2 chunks in flight
    load_chunk(Ahi, Bhi, rowbA, rowbB, 0, sb, tid);
    cp_commit();
    load_chunk(Ahi, Bhi, rowbA, rowbB, 128, sb + STAGE_BYTES, tid);
    cp_commit();

    for (int c = 0; c < NCHUNK; c++) {
        if (c < NCHUNK - 1) cp_wait<1>();
        else                cp_wait<0>();
        __syncthreads();
        if (c + 2 < NCHUNK) {
            int cn = c + 2;
            int part = cn >> 3;
            const __nv_bfloat16* As = (part == 1) ? Alo : Ahi;
            const __nv_bfloat16* Bs = (part == 2) ? Blo : Bhi;
            load_chunk(As, Bs, rowbA, rowbB, (cn & 7) * 128, sb + (cn % NSTAGE) * STAGE_BYTES, tid);
            cp_commit();
        }

        uint32_t stA = sb + (c % NSTAGE) * STAGE_BYTES;
        uint32_t stB = stA + 16384;
#pragma unroll
        for (int kt = 0; kt < 4; kt++) {
            uint32_t af[4][4], bf[4][2];
#pragma unroll
            for (int mt = 0; mt < 4; mt++) {
                int r = arow + mt * 16;
                int kb = kt * 32 + akb;
                uint32_t ad = stA + r * 128 + (kb ^ ((r & 7) * 16));
                ldsm_x4(af[mt][0], af[mt][1], af[mt][2], af[mt][3], ad);
            }
#pragma unroll
            for (int ntp = 0; ntp < 2; ntp++) {
                int r = brow + ntp * 16;
                int kb = kt * 32 + bkb;
                uint32_t bd = stB + r * 128 + (kb ^ ((r & 7) * 16));
                ldsm_x4(bf[2 * ntp][0], bf[2 * ntp][1], bf[2 * ntp + 1][0], bf[2 * ntp + 1][1], bd);
            }
#pragma unroll
            for (int mt = 0; mt < 4; mt++)
#pragma unroll
                for (int nt = 0; nt < 4; nt++)
                    mma_bf16(acc[mt][nt], af[mt], bf[nt]);
        }
    }

    // ---------------- epilogue ----------------
    int lr0 = wm * 64 + (lane >> 2);
    int lc0 = wn * 32 + (lane & 3) * 2;
    float* T = (float*)smem;                 // [128][132] transpose buffer (MODE 1)
    if (MODE == 1) __syncthreads();

#pragma unroll
    for (int mt = 0; mt < 4; mt++) {
#pragma unroll
        for (int nt = 0; nt < 4; nt++) {
            float* a = acc[mt][nt];
            int lr = lr0 + mt * 16;
            int lc = lc0 + nt * 8;
            if (MODE == 1 && bx == by) {
                if (lr == lc) a[0] = 0.f;
                if (lr == lc + 1) a[1] = 0.f;
                if (lr + 8 == lc) a[2] = 0.f;
                if (lr + 8 == lc + 1) a[3] = 0.f;
            }
            size_t g0 = (size_t)(by * 128 + lr) * ldc + bx * 128 + lc;
            if (MODE == 1) {
                stg_cs_64(&C[g0], a[0], a[1]);
                stg_cs_64(&C[g0 + 8 * ldc], a[2], a[3]);
            } else {
                *(float2*)&C[g0] = make_float2(a[0], a[1]);
                *(float2*)&C[g0 + 8 * ldc] = make_float2(a[2], a[3]);
            }
            if (MODE == 1 && bx != by) {
                T[lc * 132 + lr] = a[0];
                T[(lc + 1) * 132 + lr] = a[1];
                T[lc * 132 + lr + 8] = a[2];
                T[(lc + 1) * 132 + lr + 8] = a[3];
            }
        }
    }

    if (MODE == 1 && bx != by) {
        __syncthreads();
        // coalesced mirror write-out: each warp writes one contiguous 512B row
        // segment per iteration (8 warps x 16 iters = 128 rows)
#pragma unroll
        for (int it = 0; it < 16; it++) {
            int mrow = wid + it * 8;
            const float* Tr = &T[mrow * 132 + lane * 4];
            float4 v = make_float4(Tr[0], Tr[1], Tr[2], Tr[3]);
            stg_cs_128(&C[(size_t)(bx * 128 + mrow) * ldc + by * 128 + lane * 4], v);
        }
    }
}

// ---------------- GCN aggregation (unroll-4) ----------------
// OUTS=1: conv1 -> relu -> bf16 hi/lo split (conv2 input)
// OUTS=2: conv2 -> relu -> pxh (fp32, for fc) + L2-normalized bf16 hi/lo split (dis input)
template <int OUTS>
__global__ __launch_bounds__(128) void k_agg(
    const float* __restrict__ h, const float* __restrict__ bias,
    float* __restrict__ out, __nv_bfloat16* __restrict__ OH, __nv_bfloat16* __restrict__ OL)
{
    __shared__ float red[4];
    int d = blockIdx.x;
    int t = threadIdx.x;
    const float4* h4 = (const float4*)h;
    float4 acc0 = make_float4(0.f, 0.f, 0.f, 0.f);
    float4 acc1 = make_float4(0.f, 0.f, 0.f, 0.f);
    int e = g_off[d], end = g_off[d + 1];
    for (; e + 4 <= end; e += 4) {
        int s0 = g_ssrc[e], s1 = g_ssrc[e + 1], s2 = g_ssrc[e + 2], s3 = g_ssrc[e + 3];
        float w0 = g_dinv[s0], w1 = g_dinv[s1], w2 = g_dinv[s2], w3 = g_dinv[s3];
        float4 v0 = h4[(size_t)s0 * 128 + t];
        float4 v1 = h4[(size_t)s1 * 128 + t];
        float4 v2 = h4[(size_t)s2 * 128 + t];
        float4 v3 = h4[(size_t)s3 * 128 + t];
        acc0.x += v0.x * w0; acc0.y += v0.y * w0; acc0.z += v0.z * w0; acc0.w += v0.w * w0;
        acc1.x += v1.x * w1; acc1.y += v1.y * w1; acc1.z += v1.z * w1; acc1.w += v1.w * w1;
        acc0.x += v2.x * w2; acc0.y += v2.y * w2; acc0.z += v2.z * w2; acc0.w += v2.w * w2;
        acc1.x += v3.x * w3; acc1.y += v3.y * w3; acc1.z += v3.z * w3; acc1.w += v3.w * w3;
    }
    for (; e < end; ++e) {
        int s = g_ssrc[e];
        float w = g_dinv[s];
        float4 v = h4[(size_t)s * 128 + t];
        acc0.x += v.x * w; acc0.y += v.y * w; acc0.z += v.z * w; acc0.w += v.w * w;
    }
    float4 acc = make_float4(acc0.x + acc1.x, acc0.y + acc1.y, acc0.z + acc1.z, acc0.w + acc1.w);
    float wd = g_dinv[d];
    float w2 = wd * wd;
    float4 sv = h4[(size_t)d * 128 + t];
    float4 bb = ((const float4*)bias)[t];
    float4 r;
    r.x = fmaxf(acc.x * wd + sv.x * w2 + bb.x, 0.f);
    r.y = fmaxf(acc.y * wd + sv.y * w2 + bb.y, 0.f);
    r.z = fmaxf(acc.z * wd + sv.z * w2 + bb.z, 0.f);
    r.w = fmaxf(acc.w * wd + sv.w * w2 + bb.w, 0.f);

    if (OUTS == 2) {
        // fused: write x_hid (for fc), then L2-normalize the row and emit split
        ((float4*)out)[(size_t)d * 128 + t] = r;
        float s = r.x * r.x + r.y * r.y + r.z * r.z + r.w * r.w;
#pragma unroll
        for (int o = 16; o; o >>= 1) s += __shfl_xor_sync(0xffffffffu, s, o);
        if ((t & 31) == 0) red[t >> 5] = s;
        __syncthreads();
        float tot = red[0] + red[1] + red[2] + red[3];
        float inv = (tot > 0.f) ? rsqrtf(tot) : 0.f;
        r.x *= inv; r.y *= inv; r.z *= inv; r.w *= inv;
    }

    // emit bf16 hi/lo split of r (OUTS==1: relu'd row; OUTS==2: normalized row)
    __nv_bfloat16 h0 = __float2bfloat16(r.x), h1 = __float2bfloat16(r.y);
    __nv_bfloat16 h2 = __float2bfloat16(r.z), h3 = __float2bfloat16(r.w);
    __nv_bfloat162* H2 = (__nv_bfloat162*)(OH + (size_t)d * 512 + t * 4);
    H2[0] = __nv_bfloat162(h0, h1);
    H2[1] = __nv_bfloat162(h2, h3);
    __nv_bfloat16 l0 = __float2bfloat16(r.x - __bfloat162float(h0));
    __nv_bfloat16 l1 = __float2bfloat16(r.y - __bfloat162float(h1));
    __nv_bfloat16 l2 = __float2bfloat16(r.z - __bfloat162float(h2));
    __nv_bfloat16 l3 = __float2bfloat16(r.w - __bfloat162float(h3));
    __nv_bfloat162* L2 = (__nv_bfloat162*)(OL + (size_t)d * 512 + t * 4);
    L2[0] = __nv_bfloat162(l0, l1);
    L2[1] = __nv_bfloat162(l2, l3);
}

// ---------------- launch ----------------
extern "C" void kernel_launch(void* const* d_in, const int* in_sizes, int n_in,
                              void* d_out, int out_size) {
    const float* x   = (const float*)d_in[0];
    const int*   ei  = (const int*)d_in[1];
    const float* W1  = (const float*)d_in[2];
    const float* b1  = (const float*)d_in[3];
    const float* W2  = (const float*)d_in[4];
    const float* b2  = (const float*)d_in[5];
    const float* fcW = (const float*)d_in[6];
    const float* fcb = (const float*)d_in[7];

    const int* src = ei;
    const int* dst = ei + NEDGE;

    float* outp   = (float*)d_out;
    float* logits = outp;
    float* dis    = outp + (size_t)NNODE * NO;

    float *p1, *p3, *pxh;
    cudaGetSymbolAddress((void**)&p1,  g_buf1);
    cudaGetSymbolAddress((void**)&p3,  g_buf3);
    cudaGetSymbolAddress((void**)&pxh, g_xhid);
    __nv_bfloat16 *ahi, *alo, *whi, *wlo;
    cudaGetSymbolAddress((void**)&ahi, g_Ahi);
    cudaGetSymbolAddress((void**)&alo, g_Alo);
    cudaGetSymbolAddress((void**)&whi, g_Whi);
    cudaGetSymbolAddress((void**)&wlo, g_Wlo);

    cudaFuncSetAttribute(k_mma_gemm<0>, cudaFuncAttributeMaxDynamicSharedMemorySize, SMEM_TOTAL);
    cudaFuncSetAttribute(k_mma_gemm<1>, cudaFuncAttributeMaxDynamicSharedMemorySize, SMEM_TOTAL);

    // CSR build
    k_zero<<<NNODE / 256, 256>>>();
    k_count<<<NEDGE / 1024, 256>>>(dst);
    k_scan<<<1, 1024>>>();
    k_fill<<<NEDGE / 1024, 256>>>(src, dst);

    dim3 tblk(32, 32);
    dim3 tgrd(16, 16);
    int splitGrid = NNODE * NH / (256 * 4);
    dim3 gconv(NH / 128, NNODE / 128);       // (4, 64)

    // conv1
    k_prepW<<<tgrd, tblk>>>(W1, whi, wlo);
    k_splitF<<<splitGrid, 256>>>(x, ahi, alo);
    k_mma_gemm<0><<<gconv, 256, SMEM_TOTAL>>>(ahi, alo, whi, wlo, p1, NH,
                                              nullptr, nullptr, nullptr, nullptr);
    k_agg<1><<<NNODE, 128>>>(p1, b1, nullptr, ahi, alo);
    // conv2
    k_prepW<<<tgrd, tblk>>>(W2, whi, wlo);
    k_mma_gemm<0><<<gconv, 256, SMEM_TOTAL>>>(ahi, alo, whi, wlo, p3, NH,
                                              nullptr, nullptr, nullptr, nullptr);
    k_agg<2><<<NNODE, 128>>>(p3, b2, pxh, ahi, alo);   // fused agg+relu+norm+split
    // dis GEMM + fc head in one launch (fc rides in the dis waves)
    k_mma_gemm<1><<<NTRI + NFCB, 256, SMEM_TOTAL>>>(ahi, alo, ahi, alo, dis, NNODE,
                                                    pxh, fcW, fcb, logits);
}